// round 2
// baseline (speedup 1.0000x reference)
#include <cuda_runtime.h>
#include <cstdint>

#define NROWS    256
#define TM1      131072     // outputs per row (= flips per row)
#define TROW     131073     // edc row length
#define NTHREADS 1024
#define EPT      4
#define TILE     (NTHREADS * EPT)   // 4096
#define NTILES   (TM1 / TILE)       // 32

// ---------------------------------------------------------------------------
// Fast path: fixed shape [256, 131073]. One CTA per row.
// Phase 1 reads flips exactly once (int4), packs 128 parity bits/thread, and
// collapses the 131072-element parity scan into 32 ballots + a 32-word shared
// exchange + a 5-step bitwise prefix-XOR. Phase 2 streams edc and writes out
// with the sign applied via sign-bit XOR (amp >= 0).
// __launch_bounds__(1024, 2): cap regs at 32 so 2 CTAs/SM -> 256 blocks fit in
// ONE wave (128 of 148 SMs) instead of 2 waves.
// ---------------------------------------------------------------------------
__global__ void __launch_bounds__(NTHREADS, 2)
sticky_sign_kernel(const float* __restrict__ edc,
                   const int*   __restrict__ flips,
                   float*       __restrict__ out)
{
    const int row  = blockIdx.x;
    const int tid  = threadIdx.x;
    const int lane = tid & 31;
    const int warp = tid >> 5;
    const uint32_t ltmask = (1u << lane) - 1u;

    // ---------------- Phase 1: read flips once, build parity scan ----------
    const int4* frow = reinterpret_cast<const int4*>(flips + (size_t)row * TM1) + tid;

    uint32_t bitsPack[NTILES / 8];   // 128 flip bits per thread, packed
    uint32_t lanePref = 0;           // bit k: parity of lower lanes' flips in tile k
    uint32_t wpar     = 0;           // bit k: this warp's total parity in tile k

#pragma unroll
    for (int k = 0; k < NTILES; ++k) {
        int4 f = __ldg(&frow[k * NTHREADS]);
        uint32_t p0 = (uint32_t)f.x & 1u;
        uint32_t p1 = (uint32_t)f.y & 1u;
        uint32_t p2 = (uint32_t)f.z & 1u;
        uint32_t p3 = (uint32_t)f.w & 1u;
        if (k == 0 && tid == 0) p0 = 0u;          // flips[:,0] is never applied
        uint32_t g = p0 | (p1 << 1) | (p2 << 2) | (p3 << 3);
        if ((k & 7) == 0) bitsPack[k >> 3] = 0u;
        bitsPack[k >> 3] |= g << ((k & 7) * 4);

        uint32_t tp   = (p0 ^ p1 ^ p2 ^ p3) & 1u;
        uint32_t mask = __ballot_sync(0xffffffffu, tp);
        lanePref |= (uint32_t)(__popc(mask & ltmask) & 1) << k;
        wpar     |= (uint32_t)(__popc(mask) & 1) << k;
    }

    __shared__ uint32_t sW[32];
    if (lane == 0) sW[warp] = wpar;
    __syncthreads();

    // X bit k = total parity of tile k; Y bit k = parity of warps below me in tile k
    uint32_t X = 0, Y = 0;
#pragma unroll
    for (int w = 0; w < 32; ++w) {
        uint32_t v = sW[w];
        X ^= v;
        if (w < warp) Y ^= v;
    }
    // inclusive prefix-XOR across tile bits, then shift -> exclusive tile prefix
    uint32_t PX = X;
    PX ^= PX << 1; PX ^= PX << 2; PX ^= PX << 4; PX ^= PX << 8; PX ^= PX << 16;
    // bit k = parity of ALL flips before this thread's first element of tile k
    const uint32_t startWord = (PX << 1) ^ Y ^ lanePref;

    // ---------------- Phase 2: edc diff + sqrt + sign, write out ----------
    const float* erow = edc + (size_t)row * TROW;
    float4*      orow = reinterpret_cast<float4*>(out + (size_t)row * TM1) + tid;

#pragma unroll
    for (int k = 0; k < NTILES; ++k) {
        const int t = k * TILE + tid * EPT;
        float e0 = __ldg(erow + t);
        float e1 = __ldg(erow + t + 1);
        float e2 = __ldg(erow + t + 2);
        float e3 = __ldg(erow + t + 3);
        float e4 = __ldg(erow + t + 4);     // max index 131072 < TROW: in-bounds

        uint32_t g   = (bitsPack[k >> 3] >> ((k & 7) * 4)) & 0xFu;
        uint32_t run = (startWord >> k) & 1u;

        float4 o;
        run ^= g & 1u;
        float a0 = sqrtf(fmaxf(e0 - e1, 0.0f));
        o.x = __uint_as_float(__float_as_uint(a0) ^ (run << 31));
        run ^= (g >> 1) & 1u;
        float a1 = sqrtf(fmaxf(e1 - e2, 0.0f));
        o.y = __uint_as_float(__float_as_uint(a1) ^ (run << 31));
        run ^= (g >> 2) & 1u;
        float a2 = sqrtf(fmaxf(e2 - e3, 0.0f));
        o.z = __uint_as_float(__float_as_uint(a2) ^ (run << 31));
        run ^= (g >> 3) & 1u;
        float a3 = sqrtf(fmaxf(e3 - e4, 0.0f));
        o.w = __uint_as_float(__float_as_uint(a3) ^ (run << 31));

        orow[k * NTHREADS] = o;
    }
}

// ---------------------------------------------------------------------------
// Generic fallback: any (B, T). One CTA per row, chunked block-wide parity
// scan with a carried prefix. Correctness-first; only used if sizes don't
// match the fast-path constants.
// ---------------------------------------------------------------------------
__global__ void sticky_sign_generic(const float* __restrict__ edc,
                                    const int*   __restrict__ flips,
                                    float*       __restrict__ out,
                                    int T)
{
    const int row  = blockIdx.x;
    const int n    = T - 1;
    const int tid  = threadIdx.x;
    const int lane = tid & 31;
    const int warp = tid >> 5;

    const float* erow = edc   + (size_t)row * T;
    const int*   frow = flips + (size_t)row * n;
    float*       orow = out   + (size_t)row * n;

    __shared__ uint32_t sW[32];
    __shared__ uint32_t sCarry;
    if (tid == 0) sCarry = 0u;
    const int nwarps = (blockDim.x + 31) >> 5;
    if (tid < 32) sW[tid] = 0u;
    __syncthreads();

    for (int base = 0; base < n; base += blockDim.x) {
        const int i = base + tid;
        uint32_t f = 0u;
        if (i < n && i > 0) f = (uint32_t)frow[i] & 1u;   // flips[:,0] ignored

        const uint32_t m = __ballot_sync(0xffffffffu, f);
        const uint32_t laneIncl = (uint32_t)__popc(m & ((2u << lane) - 1u)) & 1u;
        if (lane == 0) sW[warp] = (uint32_t)__popc(m) & 1u;
        __syncthreads();

        uint32_t wpre = 0u, tot = 0u;
        for (int w = 0; w < nwarps; ++w) {
            uint32_t v = sW[w];
            tot ^= v;
            if (w < warp) wpre ^= v;
        }
        const uint32_t carry = sCarry;
        const uint32_t incl  = carry ^ wpre ^ laneIncl;   // inclusive flip parity at i

        if (i < n) {
            float amp = sqrtf(fmaxf(erow[i] - erow[i + 1], 0.0f));
            orow[i] = __uint_as_float(__float_as_uint(amp) ^ (incl << 31));
        }
        __syncthreads();
        if (tid == 0) sCarry = carry ^ tot;
        __syncthreads();
    }
}

extern "C" void kernel_launch(void* const* d_in, const int* in_sizes, int n_in,
                              void* d_out, int out_size)
{
    // Identify inputs by element count (edc has B extra elements), do not
    // trust ordering.
    long long n0 = in_sizes[0];
    long long n1 = (n_in > 1) ? in_sizes[1] : 0;

    const float* edc;
    const int*   flips;
    long long ne, nf;
    if (n0 >= n1) {
        edc = (const float*)d_in[0];  flips = (const int*)d_in[1];
        ne = n0; nf = n1;
    } else {
        edc = (const float*)d_in[1];  flips = (const int*)d_in[0];
        ne = n1; nf = n0;
    }
    float* out = (float*)d_out;

    if (ne == (long long)NROWS * TROW && nf == (long long)NROWS * TM1) {
        sticky_sign_kernel<<<NROWS, NTHREADS>>>(edc, flips, out);
    } else {
        // Generic shape: B = ne - nf rows, T = ne / B columns.
        long long B = ne - nf;
        if (B <= 0) B = 1;
        int T = (int)(ne / B);
        sticky_sign_generic<<<(int)B, 256>>>(edc, flips, out, T);
    }
}